// round 17
// baseline (speedup 1.0000x reference)
#include <cuda_runtime.h>
#include <math.h>

// Problem constants (fixed by the dataset)
#define B_ 4
#define S_ 256
#define E_ 256
#define H_ 128
#define N_ (B_ * S_)   // 1024 rows total

// Scratch (static device arrays; allocation-free per harness rules)
__device__ float g_ampq2[2][N_ * E_];   // split-K partials
__device__ float g_ampk2[2][N_ * E_];
__device__ float g_V2[2][N_ * H_];
__device__ float g_V[N_ * H_];
__device__ float g_Pq[N_ * E_];   // row-major, query side
__device__ float g_Pk[N_ * E_];   // row-major, key side
__device__ float g_entq[N_];      // sum_e P * lg2(P + 1e-10)
__device__ float g_entk[N_];
__device__ float g_O[N_ * H_];    // atomically-accumulated output numerator
__device__ float g_rs[N_];        // atomically-accumulated L1 row sums
__device__ int   g_cnt[B_ * 32];  // per-(row-block, batch) completion counters

// ---------------------------------------------------------------------------
// Kernel 1 (unchanged, proven R16): split-K double-buffered GEMM, k-chunk 16
// -> 17.4 KB smem -> 2 CTAs/SM.  64x64 tile / 4x4 micro / 16 FFMA per
// 2 LDS.128.  C[1024, 640] = x @ [Wq;Wk;Wv]^T, z = K-half.  Grid 16x10x2.
// ---------------------------------------------------------------------------
__global__ __launch_bounds__(256) void k1_gemm(
    const float* __restrict__ x,
    const float* __restrict__ Wq,
    const float* __restrict__ Wk,
    const float* __restrict__ Wv)
{
    __shared__ float As[2][16][68];  // [buf][k][m], pad keeps float4 alignment
    __shared__ float Bs[2][16][68];  // [buf][k][f]

    const int m0 = blockIdx.x * 64;       // row tile (0..15)
    const int f0 = blockIdx.y * 64;       // f tile (0..9) over concat 640
    const int z  = blockIdx.z;            // K half
    const int kbase = z * 128;

    const float* Wp; float* outp; int fo, ostride;
    if (f0 < 256)      { Wp = Wq; fo = f0;       outp = g_ampq2[z]; ostride = E_; }
    else if (f0 < 512) { Wp = Wk; fo = f0 - 256; outp = g_ampk2[z]; ostride = E_; }
    else               { Wp = Wv; fo = f0 - 512; outp = g_V2[z];    ostride = H_; }

    const int tid  = threadIdx.x;
    const int tx   = tid & 15;            // f micro
    const int ty   = tid >> 4;            // m micro
    const int lrow = tid >> 2;            // 0..63 loader row
    const int lk   = (tid & 3) * 4;       // 0,4,8,12 loader k base

    const float* xg = x  + (m0 + lrow) * E_ + kbase + lk;
    const float* wg = Wp + (fo + lrow) * E_ + kbase + lk;

    float acc[4][4] = {};

    float4 a0 = *(const float4*)(xg);
    float4 b0 = *(const float4*)(wg);
    {
        As[0][lk+0][lrow] = a0.x; As[0][lk+1][lrow] = a0.y;
        As[0][lk+2][lrow] = a0.z; As[0][lk+3][lrow] = a0.w;
        Bs[0][lk+0][lrow] = b0.x; Bs[0][lk+1][lrow] = b0.y;
        Bs[0][lk+2][lrow] = b0.z; Bs[0][lk+3][lrow] = b0.w;
    }
    __syncthreads();

    #pragma unroll
    for (int c = 0; c < 8; c++) {
        const int buf = c & 1;
        if (c < 7) {                      // prefetch next chunk BEFORE compute
            const int k0 = (c + 1) * 16;
            a0 = *(const float4*)(xg + k0);
            b0 = *(const float4*)(wg + k0);
        }

        #pragma unroll
        for (int kk = 0; kk < 16; kk++) {
            float4 av = *(const float4*)&As[buf][kk][ty * 4];
            float4 bv = *(const float4*)&Bs[buf][kk][tx * 4];
            acc[0][0] = fmaf(av.x, bv.x, acc[0][0]);
            acc[0][1] = fmaf(av.x, bv.y, acc[0][1]);
            acc[0][2] = fmaf(av.x, bv.z, acc[0][2]);
            acc[0][3] = fmaf(av.x, bv.w, acc[0][3]);
            acc[1][0] = fmaf(av.y, bv.x, acc[1][0]);
            acc[1][1] = fmaf(av.y, bv.y, acc[1][1]);
            acc[1][2] = fmaf(av.y, bv.z, acc[1][2]);
            acc[1][3] = fmaf(av.y, bv.w, acc[1][3]);
            acc[2][0] = fmaf(av.z, bv.x, acc[2][0]);
            acc[2][1] = fmaf(av.z, bv.y, acc[2][1]);
            acc[2][2] = fmaf(av.z, bv.z, acc[2][2]);
            acc[2][3] = fmaf(av.z, bv.w, acc[2][3]);
            acc[3][0] = fmaf(av.w, bv.x, acc[3][0]);
            acc[3][1] = fmaf(av.w, bv.y, acc[3][1]);
            acc[3][2] = fmaf(av.w, bv.z, acc[3][2]);
            acc[3][3] = fmaf(av.w, bv.w, acc[3][3]);
        }

        if (c < 7) {                      // stage next chunk into other buffer
            const int nb = buf ^ 1;
            As[nb][lk+0][lrow] = a0.x; As[nb][lk+1][lrow] = a0.y;
            As[nb][lk+2][lrow] = a0.z; As[nb][lk+3][lrow] = a0.w;
            Bs[nb][lk+0][lrow] = b0.x; Bs[nb][lk+1][lrow] = b0.y;
            Bs[nb][lk+2][lrow] = b0.z; Bs[nb][lk+3][lrow] = b0.w;
            __syncthreads();
        }
    }

    #pragma unroll
    for (int i = 0; i < 4; i++) {
        const int row = m0 + ty * 4 + i;
        float4 v = make_float4(acc[i][0], acc[i][1], acc[i][2], acc[i][3]);
        *(float4*)&outp[row * ostride + fo + tx * 4] = v;
    }
}

// ---------------------------------------------------------------------------
// Kernel 2 (R16 + g_cnt zeroing): warp-per-row split-K combine + probs +
// entropy.  Regions 0/1 (q/k): amp = part0+part1, P = amp^2/(ssq+EPS*d^2),
// ent = sum P*lg2(P+EPS).  Region 2: V = V0+V1.  Region 3: zero g_O row,
// g_rs, and (n<128) the completion counters.  grid 512 x 256.
// ---------------------------------------------------------------------------
__global__ __launch_bounds__(256) void k2_probs(const float* __restrict__ x)
{
    const int w    = threadIdx.x >> 5;
    const int lane = threadIdx.x & 31;
    const int slot = blockIdx.x * 8 + w;       // 0..4095
    const int regn = slot >> 10;               // 0=q, 1=k, 2=V-combine, 3=zero
    const int n    = slot & 1023;

    if (regn == 3) {                           // zero accumulators for this row
        ((float4*)&g_O[n * H_])[lane] = make_float4(0.f, 0.f, 0.f, 0.f);
        if (lane == 0) {
            g_rs[n] = 0.f;
            if (n < B_ * 32) g_cnt[n] = 0;
        }
        return;
    }
    if (regn == 2) {
        const float4* v0 = (const float4*)&g_V2[0][n * H_];
        const float4* v1 = (const float4*)&g_V2[1][n * H_];
        float4*       vo = (float4*)&g_V[n * H_];
        const float4 a = v0[lane], b = v1[lane];
        vo[lane] = make_float4(a.x + b.x, a.y + b.y, a.z + b.z, a.w + b.w);
        return;
    }

    const float* a0 = (regn ? g_ampk2[0] : g_ampq2[0]) + n * E_;
    const float* a1 = (regn ? g_ampk2[1] : g_ampq2[1]) + n * E_;
    float*     Pout = (regn ? g_Pk       : g_Pq)       + n * E_;
    const float* xr = x + n * E_;

    float a[8];
    float ssa = 0.f, ssx = 0.f;
    #pragma unroll
    for (int m = 0; m < 8; m++) {
        a[m] = a0[lane + 32 * m] + a1[lane + 32 * m];
        float xv = xr[lane + 32 * m];
        ssa = fmaf(a[m], a[m], ssa);
        ssx = fmaf(xv, xv, ssx);
    }
    #pragma unroll
    for (int o = 16; o; o >>= 1) {
        ssa += __shfl_xor_sync(0xffffffffu, ssa, o);
        ssx += __shfl_xor_sync(0xffffffffu, ssx, o);
    }
    const float d   = sqrtf(ssx) + 1e-12f;
    const float inv = 1.0f / (ssa + 1e-10f * d * d);

    float ent = 0.f;
    #pragma unroll
    for (int m = 0; m < 8; m++) {
        const float P = a[m] * a[m] * inv;
        ent = fmaf(P, __log2f(P + 1e-10f), ent);
        Pout[lane + 32 * m] = P;
    }
    #pragma unroll
    for (int o = 16; o; o >>= 1)
        ent += __shfl_xor_sync(0xffffffffu, ent, o);
    if (lane == 0) (regn ? g_entk : g_entq)[n] = ent;
}

// ---------------------------------------------------------------------------
// Kernel 3 (fused, now FINAL): JS scores + masked score-block @ V-block with
// RED accumulation into g_O / g_rs, PLUS in-kernel normalize: all rows of a
// row-block share jbmax = rb>>2, so the (rb>>2+1)-th CTA to finish a
// (rb, b) group (fence-counter pattern, no spinning) divides the 8x128
// output tile by its L1 row sums and writes d_out directly.  This deletes
// the 4.3 us k3c launch.  Static smem 41.25 KB.  Grid (32, 8, 4).
// ---------------------------------------------------------------------------
__global__ __launch_bounds__(256) void k3_sv(float* __restrict__ out)
{
    const int rb = blockIdx.x;         // row block: rows 8rb..8rb+7
    const int jb = blockIdx.y;         // j block:   js  32jb..32jb+31
    const int b  = blockIdx.z;
    if (jb > (rb >> 2)) return;        // whole block above the diagonal

    __shared__ __align__(16) float sBuf[32 * 257]; // sPk (score) / sV (O phase)
    __shared__ float sP[8][256];       // [row_local][e] (8 KB)
    __shared__ float sHk[32];
    __shared__ __align__(16) float sSc[8][32];     // masked scores (1 KB)
    __shared__ int sLast;

    float (*sV)[128] = (float(*)[128])sBuf;        // alias, used after scores

    const int tid  = threadIdx.x;
    const int w    = tid >> 5;
    const int lane = tid & 31;
    const int i0 = rb * 8, j0 = jb * 32;

    // Issue V loads FIRST (4 float4/thread, coalesced); in flight through
    // staging + score phase.
    float4 vreg[4];
    {
        const float* vsrc = g_V + (b * S_ + j0) * H_;
        #pragma unroll
        for (int k = 0; k < 4; k++) {
            const int f = tid + 256 * k;         // 0..1023 float4 slots
            vreg[k] = *(const float4*)(vsrc + (f >> 5) * H_ + (f & 31) * 4);
        }
    }

    // Stage Pk rows (warp w -> rows 4w..4w+3; 8 lanes per row, coalesced)
    {
        const int row = 4 * w + (lane >> 3);
        const int fb  = lane & 7;
        const float* src = g_Pk + (b * S_ + j0 + row) * E_;
        float* dst = sBuf + row * 257;
        #pragma unroll
        for (int it = 0; it < 8; it++) {
            const int f = fb + 8 * it;          // float4 index within row
            float4 v = *(const float4*)(src + 4 * f);
            dst[4*f+0] = v.x; dst[4*f+1] = v.y;
            dst[4*f+2] = v.z; dst[4*f+3] = v.w;
        }
    }
    // Stage Pq rows (warp w -> row w, two float4 per lane, coalesced)
    {
        const float* src = g_Pq + (b * S_ + i0 + w) * E_;
        *(float4*)&sP[w][4 * lane]        = *(const float4*)(src + 4 * lane);
        *(float4*)&sP[w][128 + 4 * lane]  = *(const float4*)(src + 128 + 4 * lane);
    }
    if (tid < 32) sHk[tid] = g_entk[b * S_ + j0 + tid];
    __syncthreads();

    // --- Score phase (warp w = row i0+w, lane = j0+lane) ---
    const float hq = g_entq[b * S_ + i0 + w];
    const float hk = sHk[lane];
    const float* pkrow = sBuf + lane * 257;      // conflict-free columns

    float ac0 = 0.f, ac1 = 0.f, ac2 = 0.f, ac3 = 0.f;
    #pragma unroll 8
    for (int e = 0; e < E_; e += 4) {
        const float4 p = *(const float4*)&sP[w][e];
        const float s0 = p.x + pkrow[e + 0];
        const float s1 = p.y + pkrow[e + 1];
        const float s2 = p.z + pkrow[e + 2];
        const float s3 = p.w + pkrow[e + 3];
        ac0 = fmaf(s0, __log2f(fmaf(0.5f, s0, 1e-10f)), ac0);
        ac1 = fmaf(s1, __log2f(fmaf(0.5f, s1, 1e-10f)), ac1);
        ac2 = fmaf(s2, __log2f(fmaf(0.5f, s2, 1e-10f)), ac2);
        ac3 = fmaf(s3, __log2f(fmaf(0.5f, s3, 1e-10f)), ac3);
    }
    const float acc = (ac0 + ac1) + (ac2 + ac3);

    const int i = i0 + w, j = j0 + lane;
    const float HL = 0.34657359028f;             // 0.5 * ln(2)
    const float ms = (j <= i) ? (1.0f - HL * (hq + hk - acc)) : 0.0f;
    sSc[w][lane] = ms;

    // Per-block L1 row sum -> atomic accumulate (scores masked to 0)
    float rs = fabsf(ms);
    #pragma unroll
    for (int o = 16; o; o >>= 1) rs += __shfl_xor_sync(0xffffffffu, rs, o);
    if (lane == 0) atomicAdd(&g_rs[b * S_ + i], rs);

    __syncthreads();   // all sPk reads done; safe to overwrite sBuf with V

    // Dump V registers to the aliased smem (pure STS, conflict-free)
    #pragma unroll
    for (int k = 0; k < 4; k++) {
        const int f = tid + 256 * k;
        *(float4*)&sV[f >> 5][(f & 31) * 4] = vreg[k];
    }
    __syncthreads();

    // --- Partial O phase: O_p[8 x 128] = sSc[8 x 32] @ sV[32 x 128],
    // reduced straight into g_O via RED.  thread = (row-quad, h).
    const int h     = tid & 127;
    const int rbase = (tid >> 7) * 4;
    float acc4[4] = {};
    #pragma unroll
    for (int j4 = 0; j4 < 32; j4 += 4) {
        const float v0 = sV[j4 + 0][h];
        const float v1 = sV[j4 + 1][h];
        const float v2 = sV[j4 + 2][h];
        const float v3 = sV[j4 + 3][h];
        #pragma unroll
        for (int r = 0; r < 4; r++) {
            const float4 s = *(const float4*)&sSc[rbase + r][j4];
            acc4[r] = fmaf(s.x, v0, acc4[r]);
            acc4[r] = fmaf(s.y, v1, acc4[r]);
            acc4[r] = fmaf(s.z, v2, acc4[r]);
            acc4[r] = fmaf(s.w, v3, acc4[r]);
        }
    }
    #pragma unroll
    for (int r = 0; r < 4; r++)
        atomicAdd(&g_O[(b * S_ + i0 + rbase + r) * H_ + h], acc4[r]);

    // --- Completion-counter normalize (fence-counter, no spinning) ---
    // (rb>>2)+1 CTAs contribute to this (rb, b) group; the last one to pass
    // the fence divides the 8x128 tile by the row sums and writes d_out.
    __threadfence();                             // release our atomics
    if (tid == 0)
        sLast = (atomicAdd(&g_cnt[b * 32 + rb], 1) == (rb >> 2));
    __syncthreads();
    if (sLast) {
        __threadfence();                         // acquire others' atomics
        #pragma unroll
        for (int k = 0; k < 4; k++) {
            const int idx = tid + 256 * k;       // 0..1023
            const int rl  = idx >> 7;            // row local 0..7
            const int hh  = idx & 127;
            const int n   = b * S_ + i0 + rl;
            const float o  = __ldcg(&g_O[n * H_ + hh]);
            const float rr = __ldcg(&g_rs[n]);
            out[n * H_ + hh] = o / fmaxf(rr, 1e-12f);
        }
    }
}

// ---------------------------------------------------------------------------
// Launch. Inputs per metadata order: x, Wv, Wq, Wk (all float32).
// ---------------------------------------------------------------------------
extern "C" void kernel_launch(void* const* d_in, const int* in_sizes, int n_in,
                              void* d_out, int out_size)
{
    const float* x  = (const float*)d_in[0];
    const float* Wv = (const float*)d_in[1];
    const float* Wq = (const float*)d_in[2];
    const float* Wk = (const float*)d_in[3];
    float* out = (float*)d_out;

    k1_gemm<<<dim3(16, 10, 2), 256>>>(x, Wq, Wk, Wv);
    k2_probs<<<512, 256>>>(x);
    k3_sv<<<dim3(32, 8, 4), 256>>>(out);
}